// round 14
// baseline (speedup 1.0000x reference)
#include <cuda_runtime.h>
#include <cuda_fp16.h>
#include <math.h>

// Problem constants
#define BB   2
#define TT   2048
#define HH   1024
#define NH   16
#define HD   64
#define MM   (BB*TT)        // 4096
#define GELEM (TT*32)

// Scratch (device globals; no allocation allowed)
__device__ __half g_xn[MM*HH];
__device__ __half g_q [MM*HH];
__device__ __half g_kr[MM*HH];
__device__ __half g_vt[MM*HH];
__device__ __half g_a [MM*HH];
__device__ float  g_x1[MM*HH];
__device__ __half g_h [MM*4*HH];
__device__ __half g_wattnT [3*HH*HH];   // [N][K] fp16
__device__ __half g_waprojT[HH*HH];
__device__ __half g_wfcT   [4*HH*HH];
__device__ __half g_wmprojT[4*HH*HH];
__device__ float  g_part[512*2];

__device__ __forceinline__ unsigned pk2(float a, float b) {
    __half2 h = __floats2half2_rn(a, b);
    return *(unsigned*)&h;
}

// ---------------------------------------------------------------------------
// Weight transpose-pack: fp32 [K][N] -> fp16 [N][K]
// ---------------------------------------------------------------------------
__global__ void pack_wT_kernel(const float* __restrict__ in, __half* __restrict__ out,
                               int K, int N)
{
    __shared__ float t[64][65];
    int n0 = blockIdx.x * 64, k0 = blockIdx.y * 64;
    #pragma unroll
    for (int i = 0; i < 4; i++) {
        int c = threadIdx.x + i * 256;
        int r = c >> 4, c4 = (c & 15) * 4;
        float4 v = *(const float4*)&in[(size_t)(k0 + r) * N + n0 + c4];
        t[r][c4] = v.x; t[r][c4+1] = v.y; t[r][c4+2] = v.z; t[r][c4+3] = v.w;
    }
    __syncthreads();
    #pragma unroll
    for (int i = 0; i < 4; i++) {
        int c = threadIdx.x + i * 256;
        int r = c >> 4, c4 = (c & 15) * 4;
        __half2 a = __floats2half2_rn(t[c4][r],   t[c4+1][r]);
        __half2 b = __floats2half2_rn(t[c4+2][r], t[c4+3][r]);
        uint2 u; u.x = *(unsigned*)&a; u.y = *(unsigned*)&b;
        *(uint2*)&out[(size_t)(n0 + r) * K + k0 + c4] = u;
    }
}

// ---------------------------------------------------------------------------
// GroupNorm: stats + apply
// ---------------------------------------------------------------------------
__global__ void gn_stats_kernel(const float* __restrict__ x,
                                float* __restrict__ part)
{
    int bg = blockIdx.x >> 3;
    int slice = blockIdx.x & 7;
    int batch = bg >> 5, g = bg & 31;
    const float* xp = x + (size_t)batch * TT * HH + g * 32;
    int t = slice * 256 + threadIdx.x;
    const float4* row = (const float4*)(xp + (size_t)t * HH);
    float s = 0.f, ss = 0.f;
    #pragma unroll
    for (int i = 0; i < 8; i++) {
        float4 v = row[i];
        s  += v.x + v.y + v.z + v.w;
        ss += v.x*v.x + v.y*v.y + v.z*v.z + v.w*v.w;
    }
    __shared__ float rs[256], rss[256];
    rs[threadIdx.x] = s; rss[threadIdx.x] = ss;
    __syncthreads();
    for (int o = 128; o > 0; o >>= 1) {
        if (threadIdx.x < o) {
            rs[threadIdx.x]  += rs[threadIdx.x + o];
            rss[threadIdx.x] += rss[threadIdx.x + o];
        }
        __syncthreads();
    }
    if (threadIdx.x == 0) {
        part[blockIdx.x * 2]     = rs[0];
        part[blockIdx.x * 2 + 1] = rss[0];
    }
}

__global__ void gn_apply_kernel(const float* __restrict__ x,
                                const float* __restrict__ part,
                                const float* __restrict__ w,
                                const float* __restrict__ b,
                                __half* __restrict__ y)
{
    __shared__ float s_mean[64], s_rstd[64];
    if (threadIdx.x < 64) {
        float s = 0.f, ss = 0.f;
        #pragma unroll
        for (int i = 0; i < 8; i++) {
            s  += part[(threadIdx.x * 8 + i) * 2];
            ss += part[(threadIdx.x * 8 + i) * 2 + 1];
        }
        float mean = s * (1.0f / GELEM);
        float var  = ss * (1.0f / GELEM) - mean * mean;
        s_mean[threadIdx.x] = mean;
        s_rstd[threadIdx.x] = rsqrtf(var + 1e-5f);
    }
    __syncthreads();

    int n4 = MM * HH / 4;
    int i = blockIdx.x * blockDim.x + threadIdx.x;
    int stride = gridDim.x * blockDim.x;
    for (; i < n4; i += stride) {
        int e = i * 4;
        int ch = e & (HH - 1);
        int batch = e >> 21;
        int bg = batch * 32 + (ch >> 5);
        float mean = s_mean[bg], rstd = s_rstd[bg];
        float4 v = ((const float4*)x)[i];
        uint2 o;
        o.x = pk2((v.x - mean) * rstd * w[ch]   + b[ch],
                  (v.y - mean) * rstd * w[ch+1] + b[ch+1]);
        o.y = pk2((v.z - mean) * rstd * w[ch+2] + b[ch+2],
                  (v.w - mean) * rstd * w[ch+3] + b[ch+3]);
        *(uint2*)(y + (size_t)i * 4) = o;
    }
}

// ---------------------------------------------------------------------------
// FP16 tensor-core GEMM (m16n8k16), ldmatrix fragments, 3-stage cp.async.
// BM=BN=128, BK=64, 256 threads (8 warps 2x4), warp tile 64x32. (R13 proven)
// ---------------------------------------------------------------------------
#define GBM 128
#define GBN 128
#define GBK 64
#define APAD 72
#define A_HALFS (GBM*APAD)
#define STG_BYTES (2*GBM*APAD*2)        // 36864
#define NSTAGE 3

__device__ __forceinline__ float gelu_f(float v) {
    const float c = 0.7978845608028654f;
    float u = c * (v + 0.044715f * v * v * v);
    return 0.5f * v * (1.0f + tanhf(u));
}

__device__ __forceinline__ void mma_f16(float* d, const unsigned* a, const unsigned* b) {
    asm volatile(
        "mma.sync.aligned.m16n8k16.row.col.f32.f16.f16.f32 "
        "{%0,%1,%2,%3}, {%4,%5,%6,%7}, {%8,%9}, {%0,%1,%2,%3};"
        : "+f"(d[0]), "+f"(d[1]), "+f"(d[2]), "+f"(d[3])
        : "r"(a[0]), "r"(a[1]), "r"(a[2]), "r"(a[3]),
          "r"(b[0]), "r"(b[1]));
}

__device__ __forceinline__ void cp16(void* dst, const void* src) {
    unsigned d = (unsigned)__cvta_generic_to_shared(dst);
    asm volatile("cp.async.cg.shared.global [%0], [%1], 16;" :: "r"(d), "l"(src));
}

__device__ __forceinline__ void ldsm4(unsigned& r0, unsigned& r1, unsigned& r2,
                                      unsigned& r3, const void* p) {
    unsigned a = (unsigned)__cvta_generic_to_shared(p);
    asm volatile("ldmatrix.sync.aligned.m8n8.x4.shared.b16 {%0,%1,%2,%3}, [%4];"
                 : "=r"(r0), "=r"(r1), "=r"(r2), "=r"(r3) : "r"(a));
}

template<int MODE>
__global__ void __launch_bounds__(256, 2)
tgemm_kernel(const __half* __restrict__ A, const __half* __restrict__ BT,
             const float* __restrict__ bias, const float* __restrict__ res,
             float* __restrict__ Cf, float* __restrict__ C2, float* __restrict__ C3,
             __half* __restrict__ Ch, __half* __restrict__ KR, __half* __restrict__ VT,
             int M, int N, int K)
{
    extern __shared__ char shraw[];

    int tid  = threadIdx.x;
    int wid  = tid >> 5;
    int lane = tid & 31;
    int wm = wid >> 2;
    int wn = wid & 3;
    int lr = lane >> 2;
    int lc = lane & 3;
    int lmat = lane >> 3;
    int lrow = lane & 7;

    int bm = blockIdx.y * GBM, bn = blockIdx.x * GBN;
    const __half* Aptr = A + (size_t)bm * K;
    const __half* Bptr = BT + (size_t)bn * K;

    float acc[4][4][4];
    #pragma unroll
    for (int i = 0; i < 4; i++)
        #pragma unroll
        for (int j = 0; j < 4; j++)
            #pragma unroll
            for (int e = 0; e < 4; e++) acc[i][j][e] = 0.f;

    int ntiles = K / GBK;

    #define LOAD_TILE(stg, k0)                                                        \
    {                                                                                 \
        __half* sA = (__half*)(shraw + (stg) * STG_BYTES);                            \
        __half* sB = sA + A_HALFS;                                                    \
        _Pragma("unroll")                                                             \
        for (int r = 0; r < 4; r++) {                                                 \
            int c = tid + r * 256;                                                    \
            int row = c >> 3, ch = (c & 7) * 8;                                       \
            cp16(sA + row * APAD + ch, Aptr + (size_t)row * K + (k0) + ch);           \
            cp16(sB + row * APAD + ch, Bptr + (size_t)row * K + (k0) + ch);           \
        }                                                                             \
    }

    LOAD_TILE(0, 0);
    asm volatile("cp.async.commit_group;");
    LOAD_TILE(1, GBK);
    asm volatile("cp.async.commit_group;");

    int stage = 0, lstage = 2;
    for (int it = 0; it < ntiles; it++) {
        if (it + 2 < ntiles) {
            LOAD_TILE(lstage, (it + 2) * GBK);
        }
        asm volatile("cp.async.commit_group;");
        asm volatile("cp.async.wait_group 2;");
        __syncthreads();

        const __half* As = (const __half*)(shraw + stage * STG_BYTES);
        const __half* Bs = As + A_HALFS;

        #pragma unroll
        for (int kk = 0; kk < GBK / 16; kk++) {
            int kb = kk * 16;
            unsigned af[4][4], bf[4][2];
            #pragma unroll
            for (int i = 0; i < 4; i++) {
                int m0 = wm * 64 + i * 16;
                const __half* p = As + (size_t)(m0 + (lmat & 1) * 8 + lrow) * APAD
                                     + kb + (lmat >> 1) * 8;
                ldsm4(af[i][0], af[i][1], af[i][2], af[i][3], p);
            }
            #pragma unroll
            for (int jj = 0; jj < 2; jj++) {
                int n0 = wn * 32 + jj * 16;
                const __half* p = Bs + (size_t)(n0 + (lmat >> 1) * 8 + lrow) * APAD
                                     + kb + (lmat & 1) * 8;
                ldsm4(bf[2*jj][0], bf[2*jj][1], bf[2*jj+1][0], bf[2*jj+1][1], p);
            }
            #pragma unroll
            for (int i = 0; i < 4; i++)
                #pragma unroll
                for (int j = 0; j < 4; j++)
                    mma_f16(acc[i][j], af[i], bf[j]);
        }
        __syncthreads();

        stage = (stage + 1) % NSTAGE;
        lstage = (lstage + 1) % NSTAGE;
    }
    #undef LOAD_TILE

    #pragma unroll
    for (int i = 0; i < 4; i++) {
        int rbase = bm + wm * 64 + i * 16 + lr;
        #pragma unroll
        for (int j = 0; j < 4; j++) {
            int cbase = bn + wn * 32 + j * 8 + 2 * lc;
            #pragma unroll
            for (int e = 0; e < 4; e++) {
                int m = rbase + (e >> 1) * 8;
                int n = cbase + (e & 1);
                float val = acc[i][j][e] + bias[n];
                if (MODE == 0) {
                    int bidx = m >> 11, t = m & 2047;
                    int part = n >> 10;
                    int nn = n & 1023;
                    int h = nn >> 6, d = nn & 63;
                    size_t idx = ((((size_t)bidx * NH + h) * TT) + t) * HD + d;
                    if (part == 0) {
                        Ch[idx] = __float2half_rn(val);
                    } else if (part == 1) {
                        C2[idx] = val;
                        KR[idx] = __float2half_rn(val);
                    } else {
                        C3[idx] = val;
                        size_t vt = (((size_t)bidx * NH + h) * HD + d) * TT + t;
                        VT[vt] = __float2half_rn(val);
                    }
                } else if (MODE == 1) {
                    size_t idx = (size_t)m * N + n;
                    Cf[idx] = val + res[idx];
                } else {
                    Ch[(size_t)m * N + n] = __float2half_rn(gelu_f(val));
                }
            }
        }
    }
}

// ---------------------------------------------------------------------------
// Flash attention, BQ=128 (8 warps), 64-key tiles, 2-stage double buffer.
// ---------------------------------------------------------------------------
#define FPH 72
#define FTILEH (64*FPH)                 // one 64x64 K or V tile (halfs)
#define FSMEM_HALFS (4*FTILEH + 128*FPH)

__global__ void __launch_bounds__(256, 2)
flash_kernel(const __half* __restrict__ Q, const __half* __restrict__ Kr,
             const __half* __restrict__ Vt, __half* __restrict__ Aout)
{
    extern __shared__ char shraw[];
    __half* shh = (__half*)shraw;
    __half* Ps = shh + 4 * FTILEH;      // [128][FPH]

    int qb = blockIdx.x;                // 0..15 (128-row q tiles)
    int bh = blockIdx.y;
    int tid = threadIdx.x;
    int w   = tid >> 5;                 // 0..7, rows w*16..w*16+15
    int lane = tid & 31;
    int lr = lane >> 2;
    int lc = lane & 3;

    const __half* qbase  = Q  + ((size_t)bh * TT + (size_t)qb * 128 + w * 16) * HD;
    const __half* kbase  = Kr + (size_t)bh * TT * HD;
    const __half* vtbase = Vt + (size_t)bh * HD * TT;

    unsigned qf[4][4];
    #pragma unroll
    for (int kk = 0; kk < 4; kk++) {
        int kb = kk * 16;
        qf[kk][0] = *(const unsigned*)(qbase + (size_t)lr * HD + kb + 2*lc);
        qf[kk][1] = *(const unsigned*)(qbase + (size_t)(lr + 8) * HD + kb + 2*lc);
        qf[kk][2] = *(const unsigned*)(qbase + (size_t)lr * HD + kb + 2*lc + 8);
        qf[kk][3] = *(const unsigned*)(qbase + (size_t)(lr + 8) * HD + kb + 2*lc + 8);
    }

    float oacc[8][4];
    #pragma unroll
    for (int nb = 0; nb < 8; nb++)
        #pragma unroll
        for (int e = 0; e < 4; e++) oacc[nb][e] = 0.f;
    float m0 = -1e30f, m1 = -1e30f, l0 = 0.f, l1 = 0.f;

    // K/V tile: 64 rows x 64 halfs = 512 chunks of 16B; 256 threads x 2 iters
    #define LOAD_KV(stg, kt0)                                                         \
    {                                                                                 \
        __half* Ks = shh + (stg) * 2 * FTILEH;                                        \
        __half* Vs = Ks + FTILEH;                                                     \
        _Pragma("unroll")                                                             \
        for (int i = 0; i < 2; i++) {                                                 \
            int c = tid + i * 256;                                                    \
            int row = c >> 3, ch = (c & 7) * 8;                                       \
            cp16(Ks + row * FPH + ch, kbase + ((size_t)(kt0) * 64 + row) * HD + ch);  \
            cp16(Vs + row * FPH + ch, vtbase + (size_t)row * TT + (kt0) * 64 + ch);   \
        }                                                                             \
    }

    int ntiles = 2 * qb + 2;

    LOAD_KV(0, 0);
    asm volatile("cp.async.commit_group;");

    for (int kt = 0; kt < ntiles; kt++) {
        if (kt + 1 < ntiles) {
            LOAD_KV((kt + 1) & 1, kt + 1);
        }
        asm volatile("cp.async.commit_group;");
        asm volatile("cp.async.wait_group 1;");
        __syncthreads();

        const __half* Ks = shh + (kt & 1) * 2 * FTILEH;
        const __half* Vs = Ks + FTILEH;

        float sacc[8][4];
        #pragma unroll
        for (int nb = 0; nb < 8; nb++)
            #pragma unroll
            for (int e = 0; e < 4; e++) sacc[nb][e] = 0.f;

        #pragma unroll
        for (int kk = 0; kk < 4; kk++) {
            int kb = kk * 16;
            #pragma unroll
            for (int nb = 0; nb < 8; nb++) {
                unsigned bf[2];
                bf[0] = *(const unsigned*)(Ks + (size_t)(nb * 8 + lr) * FPH + kb + 2*lc);
                bf[1] = *(const unsigned*)(Ks + (size_t)(nb * 8 + lr) * FPH + kb + 2*lc + 8);
                mma_f16(sacc[nb], qf[kk], bf);
            }
        }

        if (kt >= 2 * qb) {   // diagonal region: general causal mask
            int r0 = qb * 128 + w * 16 + lr, r1 = r0 + 8;
            int cb = kt * 64;
            #pragma unroll
            for (int nb = 0; nb < 8; nb++) {
                int c0 = cb + nb * 8 + 2 * lc, c1 = c0 + 1;
                if (c0 > r0) sacc[nb][0] = -1e30f;
                if (c1 > r0) sacc[nb][1] = -1e30f;
                if (c0 > r1) sacc[nb][2] = -1e30f;
                if (c1 > r1) sacc[nb][3] = -1e30f;
            }
        }

        float mx0 = -1e30f, mx1 = -1e30f;
        #pragma unroll
        for (int nb = 0; nb < 8; nb++) {
            mx0 = fmaxf(mx0, fmaxf(sacc[nb][0], sacc[nb][1]));
            mx1 = fmaxf(mx1, fmaxf(sacc[nb][2], sacc[nb][3]));
        }
        mx0 = fmaxf(mx0, __shfl_xor_sync(~0u, mx0, 1));
        mx0 = fmaxf(mx0, __shfl_xor_sync(~0u, mx0, 2));
        mx1 = fmaxf(mx1, __shfl_xor_sync(~0u, mx1, 1));
        mx1 = fmaxf(mx1, __shfl_xor_sync(~0u, mx1, 2));

        float mn0 = fmaxf(m0, mx0), mn1 = fmaxf(m1, mx1);
        float al0 = __expf(m0 - mn0), al1 = __expf(m1 - mn1);
        float sum0 = 0.f, sum1 = 0.f;
        #pragma unroll
        for (int nb = 0; nb < 8; nb++) {
            float p0 = __expf(sacc[nb][0] - mn0);
            float p1 = __expf(sacc[nb][1] - mn0);
            float p2 = __expf(sacc[nb][2] - mn1);
            float p3 = __expf(sacc[nb][3] - mn1);
            sum0 += p0 + p1; sum1 += p2 + p3;
            *(unsigned*)(Ps + (size_t)(w * 16 + lr) * FPH + nb * 8 + 2*lc)     = pk2(p0, p1);
            *(unsigned*)(Ps + (size_t)(w * 16 + lr + 8) * FPH + nb * 8 + 2*lc) = pk2(p2, p3);
        }
        sum0 += __shfl_xor_sync(~0u, sum0, 1);
        sum0 += __shfl_xor_sync(~0u, sum0, 2);
        sum1 += __shfl_xor_sync(~0u, sum1, 1);
        sum1 += __shfl_xor_sync(~0u, sum1, 2);
        l0 = l0 * al0 + sum0; l1 = l1 * al1 + sum1;
        m0 = mn0; m1 = mn1;
        #pragma unroll
        for (int nb = 0; nb < 8; nb++) {
            oacc[nb][0] *= al0; oacc[nb][1] *= al0;
            oacc[nb][2] *= al1; oacc[nb][3] *= al1;
        }
        __syncwarp();

        #pragma unroll
        for (int kk = 0; kk < 4; kk++) {
            int kb = kk * 16;
            unsigned af[4];
            af[0] = *(const unsigned*)(Ps + (size_t)(w * 16 + lr) * FPH + kb + 2*lc);
            af[1] = *(const unsigned*)(Ps + (size_t)(w * 16 + lr + 8) * FPH + kb + 2*lc);
            af[2] = *(const unsigned*)(Ps + (size_t)(w * 16 + lr) * FPH + kb + 2*lc + 8);
            af[3] = *(const unsigned*)(Ps + (size_t)(w * 16 + lr + 8) * FPH + kb + 2*lc + 8);
            #pragma unroll
            for (int nb = 0; nb < 8; nb++) {
                unsigned bf[2];
                bf[0] = *(const unsigned*)(Vs + (size_t)(nb * 8 + lr) * FPH + kb + 2*lc);
                bf[1] = *(const unsigned*)(Vs + (size_t)(nb * 8 + lr) * FPH + kb + 2*lc + 8);
                mma_f16(oacc[nb], af, bf);
            }
        }
        __syncthreads();
    }
    #undef LOAD_KV

    int batch = bh >> 4, h = bh & 15;
    float inv0 = 1.0f / l0, inv1 = 1.0f / l1;
    int t0 = qb * 128 + w * 16 + lr;
    #pragma unroll
    for (int nb = 0; nb < 8; nb++) {
        int d0 = h * HD + nb * 8 + 2 * lc;
        *(unsigned*)(Aout + ((size_t)batch * TT + t0) * HH + d0)     = pk2(oacc[nb][0] * inv0, oacc[nb][1] * inv0);
        *(unsigned*)(Aout + ((size_t)batch * TT + t0 + 8) * HH + d0) = pk2(oacc[nb][2] * inv1, oacc[nb][3] * inv1);
    }
}

// ---------------------------------------------------------------------------
// Launch
// ---------------------------------------------------------------------------
extern "C" void kernel_launch(void* const* d_in, const int* in_sizes, int n_in,
                              void* d_out, int out_size)
{
    const float* x       = (const float*)d_in[0];
    const float* w_attn  = (const float*)d_in[1];
    const float* b_attn  = (const float*)d_in[2];
    const float* w_aproj = (const float*)d_in[3];
    const float* b_aproj = (const float*)d_in[4];
    const float* ln1_w   = (const float*)d_in[5];
    const float* ln1_b   = (const float*)d_in[6];
    const float* ln2_w   = (const float*)d_in[7];
    const float* ln2_b   = (const float*)d_in[8];
    const float* w_fc    = (const float*)d_in[9];
    const float* b_fc    = (const float*)d_in[10];
    const float* w_mproj = (const float*)d_in[11];
    const float* b_mproj = (const float*)d_in[12];

    float* out_x = (float*)d_out;
    float* pk = out_x + (size_t)MM * HH;
    float* pv = pk + (size_t)MM * HH;

    __half *xn, *q, *kr, *vt, *a, *h, *wattnT, *waprojT, *wfcT, *wmprojT;
    float *x1, *part;
    cudaGetSymbolAddress((void**)&xn, g_xn);
    cudaGetSymbolAddress((void**)&q,  g_q);
    cudaGetSymbolAddress((void**)&kr, g_kr);
    cudaGetSymbolAddress((void**)&vt, g_vt);
    cudaGetSymbolAddress((void**)&a,  g_a);
    cudaGetSymbolAddress((void**)&x1, g_x1);
    cudaGetSymbolAddress((void**)&h,  g_h);
    cudaGetSymbolAddress((void**)&part, g_part);
    cudaGetSymbolAddress((void**)&wattnT,  g_wattnT);
    cudaGetSymbolAddress((void**)&waprojT, g_waprojT);
    cudaGetSymbolAddress((void**)&wfcT,    g_wfcT);
    cudaGetSymbolAddress((void**)&wmprojT, g_wmprojT);

    size_t gsmem = NSTAGE * STG_BYTES;   // 110592 B
    cudaFuncSetAttribute(tgemm_kernel<0>, cudaFuncAttributeMaxDynamicSharedMemorySize, (int)gsmem);
    cudaFuncSetAttribute(tgemm_kernel<1>, cudaFuncAttributeMaxDynamicSharedMemorySize, (int)gsmem);
    cudaFuncSetAttribute(tgemm_kernel<2>, cudaFuncAttributeMaxDynamicSharedMemorySize, (int)gsmem);
    size_t fsmem = FSMEM_HALFS * 2;      // 55296 B
    cudaFuncSetAttribute(flash_kernel, cudaFuncAttributeMaxDynamicSharedMemorySize, (int)fsmem);

    pack_wT_kernel<<<dim3(48, 16), 256>>>(w_attn,  wattnT,  HH, 3 * HH);
    pack_wT_kernel<<<dim3(16, 16), 256>>>(w_aproj, waprojT, HH, HH);
    pack_wT_kernel<<<dim3(64, 16), 256>>>(w_fc,    wfcT,    HH, 4 * HH);
    pack_wT_kernel<<<dim3(16, 64), 256>>>(w_mproj, wmprojT, 4 * HH, HH);

    gn_stats_kernel<<<512, 256>>>(x, part);
    gn_apply_kernel<<<1024, 256>>>(x, part, ln1_w, ln1_b, xn);

    tgemm_kernel<0><<<dim3(3 * HH / GBN, MM / GBM), 256, gsmem>>>(
        xn, wattnT, b_attn, nullptr, nullptr, pk, pv, q, kr, vt, MM, 3 * HH, HH);

    flash_kernel<<<dim3(TT / 128, BB * NH), 256, fsmem>>>(q, kr, vt, a);

    tgemm_kernel<1><<<dim3(HH / GBN, MM / GBM), 256, gsmem>>>(
        a, waprojT, b_aproj, x, x1, nullptr, nullptr, nullptr, nullptr, nullptr, MM, HH, HH);

    gn_stats_kernel<<<512, 256>>>(x1, part);
    gn_apply_kernel<<<1024, 256>>>(x1, part, ln2_w, ln2_b, xn);

    tgemm_kernel<2><<<dim3(4 * HH / GBN, MM / GBM), 256, gsmem>>>(
        xn, wfcT, b_fc, nullptr, nullptr, nullptr, nullptr, h, nullptr, nullptr, MM, 4 * HH, HH);

    tgemm_kernel<1><<<dim3(HH / GBN, MM / GBM), 256, gsmem>>>(
        h, wmprojT, b_mproj, x1, out_x, nullptr, nullptr, nullptr, nullptr, nullptr, MM, HH, 4 * HH);
}

// round 15
// speedup vs baseline: 1.0322x; 1.0322x over previous
#include <cuda_runtime.h>
#include <cuda_fp16.h>
#include <math.h>

// Problem constants
#define BB   2
#define TT   2048
#define HH   1024
#define NH   16
#define HD   64
#define MM   (BB*TT)        // 4096
#define GELEM (TT*32)

// Scratch (device globals; no allocation allowed)
__device__ __half g_xn[MM*HH];
__device__ __half g_q [MM*HH];
__device__ __half g_kr[MM*HH];
__device__ __half g_vt[MM*HH];
__device__ __half g_a [MM*HH];
__device__ float  g_x1[MM*HH];
__device__ __half g_h [MM*4*HH];
__device__ __half g_wattnT [3*HH*HH];   // [N][K] fp16
__device__ __half g_waprojT[HH*HH];
__device__ __half g_wfcT   [4*HH*HH];
__device__ __half g_wmprojT[4*HH*HH];
__device__ float  g_part[512*2];

__device__ __forceinline__ unsigned pk2(float a, float b) {
    __half2 h = __floats2half2_rn(a, b);
    return *(unsigned*)&h;
}

// ---------------------------------------------------------------------------
// Fused weight transpose-pack: fp32 [K][N] -> fp16 [N][K], all 4 weights.
// Tile = 64x64. Block counts: wattn 48x16=768, waproj 16x16=256,
// wfc 64x16=1024, wmproj 16x64=1024. Total 3072 blocks.
// ---------------------------------------------------------------------------
__device__ __forceinline__ void packT_tile(const float* __restrict__ in,
                                           __half* __restrict__ out,
                                           int K, int N, int n0, int k0)
{
    __shared__ float t[64][65];
    #pragma unroll
    for (int i = 0; i < 4; i++) {
        int c = threadIdx.x + i * 256;
        int r = c >> 4, c4 = (c & 15) * 4;
        float4 v = *(const float4*)&in[(size_t)(k0 + r) * N + n0 + c4];
        t[r][c4] = v.x; t[r][c4+1] = v.y; t[r][c4+2] = v.z; t[r][c4+3] = v.w;
    }
    __syncthreads();
    #pragma unroll
    for (int i = 0; i < 4; i++) {
        int c = threadIdx.x + i * 256;
        int r = c >> 4, c4 = (c & 15) * 4;
        __half2 a = __floats2half2_rn(t[c4][r],   t[c4+1][r]);
        __half2 b = __floats2half2_rn(t[c4+2][r], t[c4+3][r]);
        uint2 u; u.x = *(unsigned*)&a; u.y = *(unsigned*)&b;
        *(uint2*)&out[(size_t)(n0 + r) * K + k0 + c4] = u;
    }
}

__global__ void pack_all_kernel(const float* __restrict__ wattn_f,
                                const float* __restrict__ waproj_f,
                                const float* __restrict__ wfc_f,
                                const float* __restrict__ wmproj_f,
                                __half* __restrict__ wattnT,
                                __half* __restrict__ waprojT,
                                __half* __restrict__ wfcT,
                                __half* __restrict__ wmprojT)
{
    int b = blockIdx.x;
    if (b < 768) {                       // wattn: K=HH, N=3HH, ntiles_n=48
        int n0 = (b % 48) * 64, k0 = (b / 48) * 64;
        packT_tile(wattn_f, wattnT, HH, 3 * HH, n0, k0);
    } else if (b < 1024) {               // waproj: 16x16
        b -= 768;
        int n0 = (b % 16) * 64, k0 = (b / 16) * 64;
        packT_tile(waproj_f, waprojT, HH, HH, n0, k0);
    } else if (b < 2048) {               // wfc: K=HH, N=4HH, ntiles_n=64
        b -= 1024;
        int n0 = (b % 64) * 64, k0 = (b / 64) * 64;
        packT_tile(wfc_f, wfcT, HH, 4 * HH, n0, k0);
    } else {                             // wmproj: K=4HH, N=HH, ntiles_n=16
        b -= 2048;
        int n0 = (b % 16) * 64, k0 = (b / 16) * 64;
        packT_tile(wmproj_f, wmprojT, 4 * HH, HH, n0, k0);
    }
}

// ---------------------------------------------------------------------------
// GroupNorm: stats + apply
// ---------------------------------------------------------------------------
__global__ void gn_stats_kernel(const float* __restrict__ x,
                                float* __restrict__ part)
{
    int bg = blockIdx.x >> 3;
    int slice = blockIdx.x & 7;
    int batch = bg >> 5, g = bg & 31;
    const float* xp = x + (size_t)batch * TT * HH + g * 32;
    int t = slice * 256 + threadIdx.x;
    const float4* row = (const float4*)(xp + (size_t)t * HH);
    float s = 0.f, ss = 0.f;
    #pragma unroll
    for (int i = 0; i < 8; i++) {
        float4 v = row[i];
        s  += v.x + v.y + v.z + v.w;
        ss += v.x*v.x + v.y*v.y + v.z*v.z + v.w*v.w;
    }
    __shared__ float rs[256], rss[256];
    rs[threadIdx.x] = s; rss[threadIdx.x] = ss;
    __syncthreads();
    for (int o = 128; o > 0; o >>= 1) {
        if (threadIdx.x < o) {
            rs[threadIdx.x]  += rs[threadIdx.x + o];
            rss[threadIdx.x] += rss[threadIdx.x + o];
        }
        __syncthreads();
    }
    if (threadIdx.x == 0) {
        part[blockIdx.x * 2]     = rs[0];
        part[blockIdx.x * 2 + 1] = rss[0];
    }
}

__global__ void gn_apply_kernel(const float* __restrict__ x,
                                const float* __restrict__ part,
                                const float* __restrict__ w,
                                const float* __restrict__ b,
                                __half* __restrict__ y)
{
    __shared__ float s_mean[64], s_rstd[64];
    if (threadIdx.x < 64) {
        float s = 0.f, ss = 0.f;
        #pragma unroll
        for (int i = 0; i < 8; i++) {
            s  += part[(threadIdx.x * 8 + i) * 2];
            ss += part[(threadIdx.x * 8 + i) * 2 + 1];
        }
        float mean = s * (1.0f / GELEM);
        float var  = ss * (1.0f / GELEM) - mean * mean;
        s_mean[threadIdx.x] = mean;
        s_rstd[threadIdx.x] = rsqrtf(var + 1e-5f);
    }
    __syncthreads();

    int n4 = MM * HH / 4;
    int i = blockIdx.x * blockDim.x + threadIdx.x;
    int stride = gridDim.x * blockDim.x;
    for (; i < n4; i += stride) {
        int e = i * 4;
        int ch = e & (HH - 1);
        int batch = e >> 21;
        int bg = batch * 32 + (ch >> 5);
        float mean = s_mean[bg], rstd = s_rstd[bg];
        float4 v = ((const float4*)x)[i];
        uint2 o;
        o.x = pk2((v.x - mean) * rstd * w[ch]   + b[ch],
                  (v.y - mean) * rstd * w[ch+1] + b[ch+1]);
        o.y = pk2((v.z - mean) * rstd * w[ch+2] + b[ch+2],
                  (v.w - mean) * rstd * w[ch+3] + b[ch+3]);
        *(uint2*)(y + (size_t)i * 4) = o;
    }
}

// ---------------------------------------------------------------------------
// FP16 tensor-core GEMM (m16n8k16), ldmatrix fragments, 3-stage cp.async.
// BM=BN=128, BK=64, 256 threads (8 warps 2x4), warp tile 64x32. (R13 proven)
// ---------------------------------------------------------------------------
#define GBM 128
#define GBN 128
#define GBK 64
#define APAD 72
#define A_HALFS (GBM*APAD)
#define STG_BYTES (2*GBM*APAD*2)        // 36864
#define NSTAGE 3

__device__ __forceinline__ float gelu_f(float v) {
    const float c = 0.7978845608028654f;
    float u = c * (v + 0.044715f * v * v * v);
    return 0.5f * v * (1.0f + tanhf(u));
}

__device__ __forceinline__ void mma_f16(float* d, const unsigned* a, const unsigned* b) {
    asm volatile(
        "mma.sync.aligned.m16n8k16.row.col.f32.f16.f16.f32 "
        "{%0,%1,%2,%3}, {%4,%5,%6,%7}, {%8,%9}, {%0,%1,%2,%3};"
        : "+f"(d[0]), "+f"(d[1]), "+f"(d[2]), "+f"(d[3])
        : "r"(a[0]), "r"(a[1]), "r"(a[2]), "r"(a[3]),
          "r"(b[0]), "r"(b[1]));
}

__device__ __forceinline__ void cp16(void* dst, const void* src) {
    unsigned d = (unsigned)__cvta_generic_to_shared(dst);
    asm volatile("cp.async.cg.shared.global [%0], [%1], 16;" :: "r"(d), "l"(src));
}

__device__ __forceinline__ void ldsm4(unsigned& r0, unsigned& r1, unsigned& r2,
                                      unsigned& r3, const void* p) {
    unsigned a = (unsigned)__cvta_generic_to_shared(p);
    asm volatile("ldmatrix.sync.aligned.m8n8.x4.shared.b16 {%0,%1,%2,%3}, [%4];"
                 : "=r"(r0), "=r"(r1), "=r"(r2), "=r"(r3) : "r"(a));
}

template<int MODE>
__global__ void __launch_bounds__(256, 2)
tgemm_kernel(const __half* __restrict__ A, const __half* __restrict__ BT,
             const float* __restrict__ bias, const float* __restrict__ res,
             float* __restrict__ Cf, float* __restrict__ C2, float* __restrict__ C3,
             __half* __restrict__ Ch, __half* __restrict__ KR, __half* __restrict__ VT,
             int M, int N, int K)
{
    extern __shared__ char shraw[];

    int tid  = threadIdx.x;
    int wid  = tid >> 5;
    int lane = tid & 31;
    int wm = wid >> 2;
    int wn = wid & 3;
    int lr = lane >> 2;
    int lc = lane & 3;
    int lmat = lane >> 3;
    int lrow = lane & 7;

    int bm = blockIdx.y * GBM, bn = blockIdx.x * GBN;
    const __half* Aptr = A + (size_t)bm * K;
    const __half* Bptr = BT + (size_t)bn * K;

    float acc[4][4][4];
    #pragma unroll
    for (int i = 0; i < 4; i++)
        #pragma unroll
        for (int j = 0; j < 4; j++)
            #pragma unroll
            for (int e = 0; e < 4; e++) acc[i][j][e] = 0.f;

    int ntiles = K / GBK;

    #define LOAD_TILE(stg, k0)                                                        \
    {                                                                                 \
        __half* sA = (__half*)(shraw + (stg) * STG_BYTES);                            \
        __half* sB = sA + A_HALFS;                                                    \
        _Pragma("unroll")                                                             \
        for (int r = 0; r < 4; r++) {                                                 \
            int c = tid + r * 256;                                                    \
            int row = c >> 3, ch = (c & 7) * 8;                                       \
            cp16(sA + row * APAD + ch, Aptr + (size_t)row * K + (k0) + ch);           \
            cp16(sB + row * APAD + ch, Bptr + (size_t)row * K + (k0) + ch);           \
        }                                                                             \
    }

    LOAD_TILE(0, 0);
    asm volatile("cp.async.commit_group;");
    LOAD_TILE(1, GBK);
    asm volatile("cp.async.commit_group;");

    int stage = 0, lstage = 2;
    for (int it = 0; it < ntiles; it++) {
        if (it + 2 < ntiles) {
            LOAD_TILE(lstage, (it + 2) * GBK);
        }
        asm volatile("cp.async.commit_group;");
        asm volatile("cp.async.wait_group 2;");
        __syncthreads();

        const __half* As = (const __half*)(shraw + stage * STG_BYTES);
        const __half* Bs = As + A_HALFS;

        #pragma unroll
        for (int kk = 0; kk < GBK / 16; kk++) {
            int kb = kk * 16;
            unsigned af[4][4], bf[4][2];
            #pragma unroll
            for (int i = 0; i < 4; i++) {
                int m0 = wm * 64 + i * 16;
                const __half* p = As + (size_t)(m0 + (lmat & 1) * 8 + lrow) * APAD
                                     + kb + (lmat >> 1) * 8;
                ldsm4(af[i][0], af[i][1], af[i][2], af[i][3], p);
            }
            #pragma unroll
            for (int jj = 0; jj < 2; jj++) {
                int n0 = wn * 32 + jj * 16;
                const __half* p = Bs + (size_t)(n0 + (lmat >> 1) * 8 + lrow) * APAD
                                     + kb + (lmat & 1) * 8;
                ldsm4(bf[2*jj][0], bf[2*jj][1], bf[2*jj+1][0], bf[2*jj+1][1], p);
            }
            #pragma unroll
            for (int i = 0; i < 4; i++)
                #pragma unroll
                for (int j = 0; j < 4; j++)
                    mma_f16(acc[i][j], af[i], bf[j]);
        }
        __syncthreads();

        stage = (stage + 1) % NSTAGE;
        lstage = (lstage + 1) % NSTAGE;
    }
    #undef LOAD_TILE

    #pragma unroll
    for (int i = 0; i < 4; i++) {
        int rbase = bm + wm * 64 + i * 16 + lr;
        #pragma unroll
        for (int j = 0; j < 4; j++) {
            int cbase = bn + wn * 32 + j * 8 + 2 * lc;
            #pragma unroll
            for (int e = 0; e < 4; e++) {
                int m = rbase + (e >> 1) * 8;
                int n = cbase + (e & 1);
                float val = acc[i][j][e] + bias[n];
                if (MODE == 0) {
                    int bidx = m >> 11, t = m & 2047;
                    int part = n >> 10;
                    int nn = n & 1023;
                    int h = nn >> 6, d = nn & 63;
                    size_t idx = ((((size_t)bidx * NH + h) * TT) + t) * HD + d;
                    if (part == 0) {
                        Ch[idx] = __float2half_rn(val);
                    } else if (part == 1) {
                        C2[idx] = val;
                        KR[idx] = __float2half_rn(val);
                    } else {
                        C3[idx] = val;
                        size_t vt = (((size_t)bidx * NH + h) * HD + d) * TT + t;
                        VT[vt] = __float2half_rn(val);
                    }
                } else if (MODE == 1) {
                    size_t idx = (size_t)m * N + n;
                    Cf[idx] = val + res[idx];
                } else {
                    Ch[(size_t)m * N + n] = __float2half_rn(gelu_f(val));
                }
            }
        }
    }
}

// ---------------------------------------------------------------------------
// Flash attention, BQ=64 (4 warps), 2-stage K/V double buffer. (R13 proven)
// ---------------------------------------------------------------------------
#define FPH 72
#define FTILEH (64*FPH)

__global__ void __launch_bounds__(128, 3)
flash_kernel(const __half* __restrict__ Q, const __half* __restrict__ Kr,
             const __half* __restrict__ Vt, __half* __restrict__ Aout)
{
    extern __shared__ char shraw[];
    __half* shh = (__half*)shraw;
    __half* Ps = shh + 4 * FTILEH;

    int qb = blockIdx.x;
    int bh = blockIdx.y;
    int tid = threadIdx.x;
    int w   = tid >> 5;
    int lane = tid & 31;
    int lr = lane >> 2;
    int lc = lane & 3;

    const __half* qbase  = Q  + ((size_t)bh * TT + (size_t)qb * 64 + w * 16) * HD;
    const __half* kbase  = Kr + (size_t)bh * TT * HD;
    const __half* vtbase = Vt + (size_t)bh * HD * TT;

    unsigned qf[4][4];
    #pragma unroll
    for (int kk = 0; kk < 4; kk++) {
        int kb = kk * 16;
        qf[kk][0] = *(const unsigned*)(qbase + (size_t)lr * HD + kb + 2*lc);
        qf[kk][1] = *(const unsigned*)(qbase + (size_t)(lr + 8) * HD + kb + 2*lc);
        qf[kk][2] = *(const unsigned*)(qbase + (size_t)lr * HD + kb + 2*lc + 8);
        qf[kk][3] = *(const unsigned*)(qbase + (size_t)(lr + 8) * HD + kb + 2*lc + 8);
    }

    float oacc[8][4];
    #pragma unroll
    for (int nb = 0; nb < 8; nb++)
        #pragma unroll
        for (int e = 0; e < 4; e++) oacc[nb][e] = 0.f;
    float m0 = -1e30f, m1 = -1e30f, l0 = 0.f, l1 = 0.f;

    #define LOAD_KV(stg, kt0)                                                         \
    {                                                                                 \
        __half* Ks = shh + (stg) * 2 * FTILEH;                                        \
        __half* Vs = Ks + FTILEH;                                                     \
        _Pragma("unroll")                                                             \
        for (int i = 0; i < 4; i++) {                                                 \
            int c = tid + i * 128;                                                    \
            int row = c >> 3, ch = (c & 7) * 8;                                       \
            cp16(Ks + row * FPH + ch, kbase + ((size_t)(kt0) * 64 + row) * HD + ch);  \
            cp16(Vs + row * FPH + ch, vtbase + (size_t)row * TT + (kt0) * 64 + ch);   \
        }                                                                             \
    }

    LOAD_KV(0, 0);
    asm volatile("cp.async.commit_group;");

    for (int kt = 0; kt <= qb; kt++) {
        if (kt + 1 <= qb) {
            LOAD_KV((kt + 1) & 1, kt + 1);
        }
        asm volatile("cp.async.commit_group;");
        asm volatile("cp.async.wait_group 1;");
        __syncthreads();

        const __half* Ks = shh + (kt & 1) * 2 * FTILEH;
        const __half* Vs = Ks + FTILEH;

        float sacc[8][4];
        #pragma unroll
        for (int nb = 0; nb < 8; nb++)
            #pragma unroll
            for (int e = 0; e < 4; e++) sacc[nb][e] = 0.f;

        #pragma unroll
        for (int kk = 0; kk < 4; kk++) {
            int kb = kk * 16;
            #pragma unroll
            for (int nb = 0; nb < 8; nb++) {
                unsigned bf[2];
                bf[0] = *(const unsigned*)(Ks + (size_t)(nb * 8 + lr) * FPH + kb + 2*lc);
                bf[1] = *(const unsigned*)(Ks + (size_t)(nb * 8 + lr) * FPH + kb + 2*lc + 8);
                mma_f16(sacc[nb], qf[kk], bf);
            }
        }

        if (kt == qb) {
            int r0 = w * 16 + lr, r1 = r0 + 8;
            #pragma unroll
            for (int nb = 0; nb < 8; nb++) {
                int c0 = nb * 8 + 2 * lc, c1 = c0 + 1;
                if (c0 > r0) sacc[nb][0] = -1e30f;
                if (c1 > r0) sacc[nb][1] = -1e30f;
                if (c0 > r1) sacc[nb][2] = -1e30f;
                if (c1 > r1) sacc[nb][3] = -1e30f;
            }
        }

        float mx0 = -1e30f, mx1 = -1e30f;
        #pragma unroll
        for (int nb = 0; nb < 8; nb++) {
            mx0 = fmaxf(mx0, fmaxf(sacc[nb][0], sacc[nb][1]));
            mx1 = fmaxf(mx1, fmaxf(sacc[nb][2], sacc[nb][3]));
        }
        mx0 = fmaxf(mx0, __shfl_xor_sync(~0u, mx0, 1));
        mx0 = fmaxf(mx0, __shfl_xor_sync(~0u, mx0, 2));
        mx1 = fmaxf(mx1, __shfl_xor_sync(~0u, mx1, 1));
        mx1 = fmaxf(mx1, __shfl_xor_sync(~0u, mx1, 2));

        float mn0 = fmaxf(m0, mx0), mn1 = fmaxf(m1, mx1);
        float al0 = __expf(m0 - mn0), al1 = __expf(m1 - mn1);
        float sum0 = 0.f, sum1 = 0.f;
        #pragma unroll
        for (int nb = 0; nb < 8; nb++) {
            float p0 = __expf(sacc[nb][0] - mn0);
            float p1 = __expf(sacc[nb][1] - mn0);
            float p2 = __expf(sacc[nb][2] - mn1);
            float p3 = __expf(sacc[nb][3] - mn1);
            sum0 += p0 + p1; sum1 += p2 + p3;
            *(unsigned*)(Ps + (size_t)(w * 16 + lr) * FPH + nb * 8 + 2*lc)     = pk2(p0, p1);
            *(unsigned*)(Ps + (size_t)(w * 16 + lr + 8) * FPH + nb * 8 + 2*lc) = pk2(p2, p3);
        }
        sum0 += __shfl_xor_sync(~0u, sum0, 1);
        sum0 += __shfl_xor_sync(~0u, sum0, 2);
        sum1 += __shfl_xor_sync(~0u, sum1, 1);
        sum1 += __shfl_xor_sync(~0u, sum1, 2);
        l0 = l0 * al0 + sum0; l1 = l1 * al1 + sum1;
        m0 = mn0; m1 = mn1;
        #pragma unroll
        for (int nb = 0; nb < 8; nb++) {
            oacc[nb][0] *= al0; oacc[nb][1] *= al0;
            oacc[nb][2] *= al1; oacc[nb][3] *= al1;
        }
        __syncwarp();

        #pragma unroll
        for (int kk = 0; kk < 4; kk++) {
            int kb = kk * 16;
            unsigned af[4];
            af[0] = *(const unsigned*)(Ps + (size_t)(w * 16 + lr) * FPH + kb + 2*lc);
            af[1] = *(const unsigned*)(Ps + (size_t)(w * 16 + lr + 8) * FPH + kb + 2*lc);
            af[2] = *(const unsigned*)(Ps + (size_t)(w * 16 + lr) * FPH + kb + 2*lc + 8);
            af[3] = *(const unsigned*)(Ps + (size_t)(w * 16 + lr + 8) * FPH + kb + 2*lc + 8);
            #pragma unroll
            for (int nb = 0; nb < 8; nb++) {
                unsigned bf[2];
                bf[0] = *(const unsigned*)(Vs + (size_t)(nb * 8 + lr) * FPH + kb + 2*lc);
                bf[1] = *(const unsigned*)(Vs + (size_t)(nb * 8 + lr) * FPH + kb + 2*lc + 8);
                mma_f16(oacc[nb], af, bf);
            }
        }
        __syncthreads();
    }
    #undef LOAD_KV

    int batch = bh >> 4, h = bh & 15;
    float inv0 = 1.0f / l0, inv1 = 1.0f / l1;
    int t0 = qb * 64 + w * 16 + lr;
    #pragma unroll
    for (int nb = 0; nb < 8; nb++) {
        int d0 = h * HD + nb * 8 + 2 * lc;
        *(unsigned*)(Aout + ((size_t)batch * TT + t0) * HH + d0)     = pk2(oacc[nb][0] * inv0, oacc[nb][1] * inv0);
        *(unsigned*)(Aout + ((size_t)batch * TT + t0 + 8) * HH + d0) = pk2(oacc[nb][2] * inv1, oacc[nb][3] * inv1);
    }
}

// ---------------------------------------------------------------------------
// Launch
// ---------------------------------------------------------------------------
extern "C" void kernel_launch(void* const* d_in, const int* in_sizes, int n_in,
                              void* d_out, int out_size)
{
    const float* x       = (const float*)d_in[0];
    const float* w_attn  = (const float*)d_in[1];
    const float* b_attn  = (const float*)d_in[2];
    const float* w_aproj = (const float*)d_in[3];
    const float* b_aproj = (const float*)d_in[4];
    const float* ln1_w   = (const float*)d_in[5];
    const float* ln1_b   = (const float*)d_in[6];
    const float* ln2_w   = (const float*)d_in[7];
    const float* ln2_b   = (const float*)d_in[8];
    const float* w_fc    = (const float*)d_in[9];
    const float* b_fc    = (const float*)d_in[10];
    const float* w_mproj = (const float*)d_in[11];
    const float* b_mproj = (const float*)d_in[12];

    float* out_x = (float*)d_out;
    float* pk = out_x + (size_t)MM * HH;
    float* pv = pk + (size_t)MM * HH;

    __half *xn, *q, *kr, *vt, *a, *h, *wattnT, *waprojT, *wfcT, *wmprojT;
    float *x1, *part;
    cudaGetSymbolAddress((void**)&xn, g_xn);
    cudaGetSymbolAddress((void**)&q,  g_q);
    cudaGetSymbolAddress((void**)&kr, g_kr);
    cudaGetSymbolAddress((void**)&vt, g_vt);
    cudaGetSymbolAddress((void**)&a,  g_a);
    cudaGetSymbolAddress((void**)&x1, g_x1);
    cudaGetSymbolAddress((void**)&h,  g_h);
    cudaGetSymbolAddress((void**)&part, g_part);
    cudaGetSymbolAddress((void**)&wattnT,  g_wattnT);
    cudaGetSymbolAddress((void**)&waprojT, g_waprojT);
    cudaGetSymbolAddress((void**)&wfcT,    g_wfcT);
    cudaGetSymbolAddress((void**)&wmprojT, g_wmprojT);

    size_t gsmem = NSTAGE * STG_BYTES;   // 110592 B
    cudaFuncSetAttribute(tgemm_kernel<0>, cudaFuncAttributeMaxDynamicSharedMemorySize, (int)gsmem);
    cudaFuncSetAttribute(tgemm_kernel<1>, cudaFuncAttributeMaxDynamicSharedMemorySize, (int)gsmem);
    cudaFuncSetAttribute(tgemm_kernel<2>, cudaFuncAttributeMaxDynamicSharedMemorySize, (int)gsmem);
    size_t fsmem = 5 * FTILEH * 2;       // 46080 B
    cudaFuncSetAttribute(flash_kernel, cudaFuncAttributeMaxDynamicSharedMemorySize, (int)fsmem);

    pack_all_kernel<<<3072, 256>>>(w_attn, w_aproj, w_fc, w_mproj,
                                   wattnT, waprojT, wfcT, wmprojT);

    gn_stats_kernel<<<512, 256>>>(x, part);
    gn_apply_kernel<<<1024, 256>>>(x, part, ln1_w, ln1_b, xn);

    tgemm_kernel<0><<<dim3(3 * HH / GBN, MM / GBM), 256, gsmem>>>(
        xn, wattnT, b_attn, nullptr, nullptr, pk, pv, q, kr, vt, MM, 3 * HH, HH);

    flash_kernel<<<dim3(TT / 64, BB * NH), 128, fsmem>>>(q, kr, vt, a);

    tgemm_kernel<1><<<dim3(HH / GBN, MM / GBM), 256, gsmem>>>(
        a, waprojT, b_aproj, x, x1, nullptr, nullptr, nullptr, nullptr, nullptr, MM, HH, HH);

    gn_stats_kernel<<<512, 256>>>(x1, part);
    gn_apply_kernel<<<1024, 256>>>(x1, part, ln2_w, ln2_b, xn);

    tgemm_kernel<2><<<dim3(4 * HH / GBN, MM / GBM), 256, gsmem>>>(
        xn, wfcT, b_fc, nullptr, nullptr, nullptr, nullptr, h, nullptr, nullptr, MM, 4 * HH, HH);

    tgemm_kernel<1><<<dim3(HH / GBN, MM / GBM), 256, gsmem>>>(
        h, wmprojT, b_mproj, x1, out_x, nullptr, nullptr, nullptr, nullptr, nullptr, MM, HH, 4 * HH);
}

// round 16
// speedup vs baseline: 1.0432x; 1.0107x over previous
#include <cuda_runtime.h>
#include <cuda_fp16.h>
#include <math.h>

// Problem constants
#define BB   2
#define TT   2048
#define HH   1024
#define NH   16
#define HD   64
#define MM   (BB*TT)        // 4096
#define GELEM (TT*32)

// Scratch (device globals; no allocation allowed)
__device__ __half g_xn[MM*HH];
__device__ __half g_q [MM*HH];
__device__ __half g_kr[MM*HH];
__device__ __half g_vt[MM*HH];
__device__ __half g_a [MM*HH];
__device__ float  g_x1[MM*HH];
__device__ __half g_h [MM*4*HH];
__device__ __half g_wattnT [3*HH*HH];   // [N][K] fp16
__device__ __half g_waprojT[HH*HH];
__device__ __half g_wfcT   [4*HH*HH];
__device__ __half g_wmprojT[4*HH*HH];
__device__ float  g_part[512*2];

__device__ __forceinline__ unsigned pk2(float a, float b) {
    __half2 h = __floats2half2_rn(a, b);
    return *(unsigned*)&h;
}

// ---------------------------------------------------------------------------
// Fused weight transpose-pack: fp32 [K][N] -> fp16 [N][K], all 4 weights.
// ---------------------------------------------------------------------------
__device__ __forceinline__ void packT_tile(const float* __restrict__ in,
                                           __half* __restrict__ out,
                                           int K, int N, int n0, int k0)
{
    __shared__ float t[64][65];
    #pragma unroll
    for (int i = 0; i < 4; i++) {
        int c = threadIdx.x + i * 256;
        int r = c >> 4, c4 = (c & 15) * 4;
        float4 v = *(const float4*)&in[(size_t)(k0 + r) * N + n0 + c4];
        t[r][c4] = v.x; t[r][c4+1] = v.y; t[r][c4+2] = v.z; t[r][c4+3] = v.w;
    }
    __syncthreads();
    #pragma unroll
    for (int i = 0; i < 4; i++) {
        int c = threadIdx.x + i * 256;
        int r = c >> 4, c4 = (c & 15) * 4;
        __half2 a = __floats2half2_rn(t[c4][r],   t[c4+1][r]);
        __half2 b = __floats2half2_rn(t[c4+2][r], t[c4+3][r]);
        uint2 u; u.x = *(unsigned*)&a; u.y = *(unsigned*)&b;
        *(uint2*)&out[(size_t)(n0 + r) * K + k0 + c4] = u;
    }
}

__global__ void pack_all_kernel(const float* __restrict__ wattn_f,
                                const float* __restrict__ waproj_f,
                                const float* __restrict__ wfc_f,
                                const float* __restrict__ wmproj_f,
                                __half* __restrict__ wattnT,
                                __half* __restrict__ waprojT,
                                __half* __restrict__ wfcT,
                                __half* __restrict__ wmprojT)
{
    int b = blockIdx.x;
    if (b < 768) {
        int n0 = (b % 48) * 64, k0 = (b / 48) * 64;
        packT_tile(wattn_f, wattnT, HH, 3 * HH, n0, k0);
    } else if (b < 1024) {
        b -= 768;
        int n0 = (b % 16) * 64, k0 = (b / 16) * 64;
        packT_tile(waproj_f, waprojT, HH, HH, n0, k0);
    } else if (b < 2048) {
        b -= 1024;
        int n0 = (b % 64) * 64, k0 = (b / 64) * 64;
        packT_tile(wfc_f, wfcT, HH, 4 * HH, n0, k0);
    } else {
        b -= 2048;
        int n0 = (b % 16) * 64, k0 = (b / 16) * 64;
        packT_tile(wmproj_f, wmprojT, 4 * HH, HH, n0, k0);
    }
}

// ---------------------------------------------------------------------------
// GroupNorm: stats + apply
// ---------------------------------------------------------------------------
__global__ void gn_stats_kernel(const float* __restrict__ x,
                                float* __restrict__ part)
{
    int bg = blockIdx.x >> 3;
    int slice = blockIdx.x & 7;
    int batch = bg >> 5, g = bg & 31;
    const float* xp = x + (size_t)batch * TT * HH + g * 32;
    int t = slice * 256 + threadIdx.x;
    const float4* row = (const float4*)(xp + (size_t)t * HH);
    float s = 0.f, ss = 0.f;
    #pragma unroll
    for (int i = 0; i < 8; i++) {
        float4 v = row[i];
        s  += v.x + v.y + v.z + v.w;
        ss += v.x*v.x + v.y*v.y + v.z*v.z + v.w*v.w;
    }
    __shared__ float rs[256], rss[256];
    rs[threadIdx.x] = s; rss[threadIdx.x] = ss;
    __syncthreads();
    for (int o = 128; o > 0; o >>= 1) {
        if (threadIdx.x < o) {
            rs[threadIdx.x]  += rs[threadIdx.x + o];
            rss[threadIdx.x] += rss[threadIdx.x + o];
        }
        __syncthreads();
    }
    if (threadIdx.x == 0) {
        part[blockIdx.x * 2]     = rs[0];
        part[blockIdx.x * 2 + 1] = rss[0];
    }
}

__global__ void gn_apply_kernel(const float* __restrict__ x,
                                const float* __restrict__ part,
                                const float* __restrict__ w,
                                const float* __restrict__ b,
                                __half* __restrict__ y)
{
    __shared__ float s_mean[64], s_rstd[64];
    if (threadIdx.x < 64) {
        float s = 0.f, ss = 0.f;
        #pragma unroll
        for (int i = 0; i < 8; i++) {
            s  += part[(threadIdx.x * 8 + i) * 2];
            ss += part[(threadIdx.x * 8 + i) * 2 + 1];
        }
        float mean = s * (1.0f / GELEM);
        float var  = ss * (1.0f / GELEM) - mean * mean;
        s_mean[threadIdx.x] = mean;
        s_rstd[threadIdx.x] = rsqrtf(var + 1e-5f);
    }
    __syncthreads();

    int n4 = MM * HH / 4;
    int i = blockIdx.x * blockDim.x + threadIdx.x;
    int stride = gridDim.x * blockDim.x;
    for (; i < n4; i += stride) {
        int e = i * 4;
        int ch = e & (HH - 1);
        int batch = e >> 21;
        int bg = batch * 32 + (ch >> 5);
        float mean = s_mean[bg], rstd = s_rstd[bg];
        float4 v = ((const float4*)x)[i];
        uint2 o;
        o.x = pk2((v.x - mean) * rstd * w[ch]   + b[ch],
                  (v.y - mean) * rstd * w[ch+1] + b[ch+1]);
        o.y = pk2((v.z - mean) * rstd * w[ch+2] + b[ch+2],
                  (v.w - mean) * rstd * w[ch+3] + b[ch+3]);
        *(uint2*)(y + (size_t)i * 4) = o;
    }
}

// ---------------------------------------------------------------------------
// FP16 tensor-core GEMM (m16n8k16), ldmatrix, 3-stage cp.async,
// SINGLE barrier per mainloop iteration.
// BM=BN=128, BK=64, 256 threads (8 warps 2x4), warp tile 64x32.
// ---------------------------------------------------------------------------
#define GBM 128
#define GBN 128
#define GBK 64
#define APAD 72
#define A_HALFS (GBM*APAD)
#define STG_BYTES (2*GBM*APAD*2)        // 36864
#define NSTAGE 3

__device__ __forceinline__ float gelu_f(float v) {
    const float c = 0.7978845608028654f;
    float u = c * (v + 0.044715f * v * v * v);
    return 0.5f * v * (1.0f + tanhf(u));
}

__device__ __forceinline__ void mma_f16(float* d, const unsigned* a, const unsigned* b) {
    asm volatile(
        "mma.sync.aligned.m16n8k16.row.col.f32.f16.f16.f32 "
        "{%0,%1,%2,%3}, {%4,%5,%6,%7}, {%8,%9}, {%0,%1,%2,%3};"
        : "+f"(d[0]), "+f"(d[1]), "+f"(d[2]), "+f"(d[3])
        : "r"(a[0]), "r"(a[1]), "r"(a[2]), "r"(a[3]),
          "r"(b[0]), "r"(b[1]));
}

__device__ __forceinline__ void cp16(void* dst, const void* src) {
    unsigned d = (unsigned)__cvta_generic_to_shared(dst);
    asm volatile("cp.async.cg.shared.global [%0], [%1], 16;" :: "r"(d), "l"(src));
}

__device__ __forceinline__ void ldsm4(unsigned& r0, unsigned& r1, unsigned& r2,
                                      unsigned& r3, const void* p) {
    unsigned a = (unsigned)__cvta_generic_to_shared(p);
    asm volatile("ldmatrix.sync.aligned.m8n8.x4.shared.b16 {%0,%1,%2,%3}, [%4];"
                 : "=r"(r0), "=r"(r1), "=r"(r2), "=r"(r3) : "r"(a));
}

template<int MODE>
__global__ void __launch_bounds__(256, 2)
tgemm_kernel(const __half* __restrict__ A, const __half* __restrict__ BT,
             const float* __restrict__ bias, const float* __restrict__ res,
             float* __restrict__ Cf, float* __restrict__ C2, float* __restrict__ C3,
             __half* __restrict__ Ch, __half* __restrict__ KR, __half* __restrict__ VT,
             int M, int N, int K)
{
    extern __shared__ char shraw[];

    int tid  = threadIdx.x;
    int wid  = tid >> 5;
    int lane = tid & 31;
    int wm = wid >> 2;
    int wn = wid & 3;
    int lr = lane >> 2;
    int lc = lane & 3;
    int lmat = lane >> 3;
    int lrow = lane & 7;

    int bm = blockIdx.y * GBM, bn = blockIdx.x * GBN;
    const __half* Aptr = A + (size_t)bm * K;
    const __half* Bptr = BT + (size_t)bn * K;

    float acc[4][4][4];
    #pragma unroll
    for (int i = 0; i < 4; i++)
        #pragma unroll
        for (int j = 0; j < 4; j++)
            #pragma unroll
            for (int e = 0; e < 4; e++) acc[i][j][e] = 0.f;

    int ntiles = K / GBK;

    #define LOAD_TILE(stg, k0)                                                        \
    {                                                                                 \
        __half* sA = (__half*)(shraw + (stg) * STG_BYTES);                            \
        __half* sB = sA + A_HALFS;                                                    \
        _Pragma("unroll")                                                             \
        for (int r = 0; r < 4; r++) {                                                 \
            int c = tid + r * 256;                                                    \
            int row = c >> 3, ch = (c & 7) * 8;                                       \
            cp16(sA + row * APAD + ch, Aptr + (size_t)row * K + (k0) + ch);           \
            cp16(sB + row * APAD + ch, Bptr + (size_t)row * K + (k0) + ch);           \
        }                                                                             \
    }

    LOAD_TILE(0, 0);
    asm volatile("cp.async.commit_group;");
    LOAD_TILE(1, GBK);
    asm volatile("cp.async.commit_group;");

    int stage = 0, lstage = 2;
    for (int it = 0; it < ntiles; it++) {
        // wait for tile `it` (all groups except the newest one are complete)
        asm volatile("cp.async.wait_group 1;");
        __syncthreads();
        // prefetch tile it+2 into lstage; that stage was last READ at iter it-1,
        // and the barrier above guarantees all warps finished that read.
        if (it + 2 < ntiles) {
            LOAD_TILE(lstage, (it + 2) * GBK);
        }
        asm volatile("cp.async.commit_group;");   // uniform (may be empty)

        const __half* As = (const __half*)(shraw + stage * STG_BYTES);
        const __half* Bs = As + A_HALFS;

        #pragma unroll
        for (int kk = 0; kk < GBK / 16; kk++) {
            int kb = kk * 16;
            unsigned af[4][4], bf[4][2];
            #pragma unroll
            for (int i = 0; i < 4; i++) {
                int m0 = wm * 64 + i * 16;
                const __half* p = As + (size_t)(m0 + (lmat & 1) * 8 + lrow) * APAD
                                     + kb + (lmat >> 1) * 8;
                ldsm4(af[i][0], af[i][1], af[i][2], af[i][3], p);
            }
            #pragma unroll
            for (int jj = 0; jj < 2; jj++) {
                int n0 = wn * 32 + jj * 16;
                const __half* p = Bs + (size_t)(n0 + (lmat >> 1) * 8 + lrow) * APAD
                                     + kb + (lmat & 1) * 8;
                ldsm4(bf[2*jj][0], bf[2*jj][1], bf[2*jj+1][0], bf[2*jj+1][1], p);
            }
            #pragma unroll
            for (int i = 0; i < 4; i++)
                #pragma unroll
                for (int j = 0; j < 4; j++)
                    mma_f16(acc[i][j], af[i], bf[j]);
        }

        stage = (stage + 1) % NSTAGE;
        lstage = (lstage + 1) % NSTAGE;
    }
    #undef LOAD_TILE

    #pragma unroll
    for (int i = 0; i < 4; i++) {
        int rbase = bm + wm * 64 + i * 16 + lr;
        #pragma unroll
        for (int j = 0; j < 4; j++) {
            int cbase = bn + wn * 32 + j * 8 + 2 * lc;
            #pragma unroll
            for (int e = 0; e < 4; e++) {
                int m = rbase + (e >> 1) * 8;
                int n = cbase + (e & 1);
                float val = acc[i][j][e] + bias[n];
                if (MODE == 0) {
                    int bidx = m >> 11, t = m & 2047;
                    int part = n >> 10;
                    int nn = n & 1023;
                    int h = nn >> 6, d = nn & 63;
                    size_t idx = ((((size_t)bidx * NH + h) * TT) + t) * HD + d;
                    if (part == 0) {
                        Ch[idx] = __float2half_rn(val);
                    } else if (part == 1) {
                        C2[idx] = val;
                        KR[idx] = __float2half_rn(val);
                    } else {
                        C3[idx] = val;
                        size_t vt = (((size_t)bidx * NH + h) * HD + d) * TT + t;
                        VT[vt] = __float2half_rn(val);
                    }
                } else if (MODE == 1) {
                    size_t idx = (size_t)m * N + n;
                    Cf[idx] = val + res[idx];
                } else {
                    Ch[(size_t)m * N + n] = __float2half_rn(gelu_f(val));
                }
            }
        }
    }
}

// ---------------------------------------------------------------------------
// Flash attention, BQ=64, 2-stage K/V double buffer, single barrier per tile.
// ---------------------------------------------------------------------------
#define FPH 72
#define FTILEH (64*FPH)

__global__ void __launch_bounds__(128, 3)
flash_kernel(const __half* __restrict__ Q, const __half* __restrict__ Kr,
             const __half* __restrict__ Vt, __half* __restrict__ Aout)
{
    extern __shared__ char shraw[];
    __half* shh = (__half*)shraw;
    __half* Ps = shh + 4 * FTILEH;

    int qb = blockIdx.x;
    int bh = blockIdx.y;
    int tid = threadIdx.x;
    int w   = tid >> 5;
    int lane = tid & 31;
    int lr = lane >> 2;
    int lc = lane & 3;

    const __half* qbase  = Q  + ((size_t)bh * TT + (size_t)qb * 64 + w * 16) * HD;
    const __half* kbase  = Kr + (size_t)bh * TT * HD;
    const __half* vtbase = Vt + (size_t)bh * HD * TT;

    unsigned qf[4][4];
    #pragma unroll
    for (int kk = 0; kk < 4; kk++) {
        int kb = kk * 16;
        qf[kk][0] = *(const unsigned*)(qbase + (size_t)lr * HD + kb + 2*lc);
        qf[kk][1] = *(const unsigned*)(qbase + (size_t)(lr + 8) * HD + kb + 2*lc);
        qf[kk][2] = *(const unsigned*)(qbase + (size_t)lr * HD + kb + 2*lc + 8);
        qf[kk][3] = *(const unsigned*)(qbase + (size_t)(lr + 8) * HD + kb + 2*lc + 8);
    }

    float oacc[8][4];
    #pragma unroll
    for (int nb = 0; nb < 8; nb++)
        #pragma unroll
        for (int e = 0; e < 4; e++) oacc[nb][e] = 0.f;
    float m0 = -1e30f, m1 = -1e30f, l0 = 0.f, l1 = 0.f;

    #define LOAD_KV(stg, kt0)                                                         \
    {                                                                                 \
        __half* Ks = shh + (stg) * 2 * FTILEH;                                        \
        __half* Vs = Ks + FTILEH;                                                     \
        _Pragma("unroll")                                                             \
        for (int i = 0; i < 4; i++) {                                                 \
            int c = tid + i * 128;                                                    \
            int row = c >> 3, ch = (c & 7) * 8;                                       \
            cp16(Ks + row * FPH + ch, kbase + ((size_t)(kt0) * 64 + row) * HD + ch);  \
            cp16(Vs + row * FPH + ch, vtbase + (size_t)row * TT + (kt0) * 64 + ch);   \
        }                                                                             \
    }

    LOAD_KV(0, 0);
    asm volatile("cp.async.commit_group;");

    for (int kt = 0; kt <= qb; kt++) {
        // wait for tile kt (newest committed group), then one barrier
        asm volatile("cp.async.wait_group 0;");
        __syncthreads();
        // prefetch kt+1 into the other stage; last read of that stage was at
        // iteration kt-1, protected by the barrier above.
        if (kt + 1 <= qb) {
            LOAD_KV((kt + 1) & 1, kt + 1);
        }
        asm volatile("cp.async.commit_group;");

        const __half* Ks = shh + (kt & 1) * 2 * FTILEH;
        const __half* Vs = Ks + FTILEH;

        float sacc[8][4];
        #pragma unroll
        for (int nb = 0; nb < 8; nb++)
            #pragma unroll
            for (int e = 0; e < 4; e++) sacc[nb][e] = 0.f;

        #pragma unroll
        for (int kk = 0; kk < 4; kk++) {
            int kb = kk * 16;
            #pragma unroll
            for (int nb = 0; nb < 8; nb++) {
                unsigned bf[2];
                bf[0] = *(const unsigned*)(Ks + (size_t)(nb * 8 + lr) * FPH + kb + 2*lc);
                bf[1] = *(const unsigned*)(Ks + (size_t)(nb * 8 + lr) * FPH + kb + 2*lc + 8);
                mma_f16(sacc[nb], qf[kk], bf);
            }
        }

        if (kt == qb) {
            int r0 = w * 16 + lr, r1 = r0 + 8;
            #pragma unroll
            for (int nb = 0; nb < 8; nb++) {
                int c0 = nb * 8 + 2 * lc, c1 = c0 + 1;
                if (c0 > r0) sacc[nb][0] = -1e30f;
                if (c1 > r0) sacc[nb][1] = -1e30f;
                if (c0 > r1) sacc[nb][2] = -1e30f;
                if (c1 > r1) sacc[nb][3] = -1e30f;
            }
        }

        float mx0 = -1e30f, mx1 = -1e30f;
        #pragma unroll
        for (int nb = 0; nb < 8; nb++) {
            mx0 = fmaxf(mx0, fmaxf(sacc[nb][0], sacc[nb][1]));
            mx1 = fmaxf(mx1, fmaxf(sacc[nb][2], sacc[nb][3]));
        }
        mx0 = fmaxf(mx0, __shfl_xor_sync(~0u, mx0, 1));
        mx0 = fmaxf(mx0, __shfl_xor_sync(~0u, mx0, 2));
        mx1 = fmaxf(mx1, __shfl_xor_sync(~0u, mx1, 1));
        mx1 = fmaxf(mx1, __shfl_xor_sync(~0u, mx1, 2));

        float mn0 = fmaxf(m0, mx0), mn1 = fmaxf(m1, mx1);
        float al0 = __expf(m0 - mn0), al1 = __expf(m1 - mn1);
        float sum0 = 0.f, sum1 = 0.f;
        #pragma unroll
        for (int nb = 0; nb < 8; nb++) {
            float p0 = __expf(sacc[nb][0] - mn0);
            float p1 = __expf(sacc[nb][1] - mn0);
            float p2 = __expf(sacc[nb][2] - mn1);
            float p3 = __expf(sacc[nb][3] - mn1);
            sum0 += p0 + p1; sum1 += p2 + p3;
            *(unsigned*)(Ps + (size_t)(w * 16 + lr) * FPH + nb * 8 + 2*lc)     = pk2(p0, p1);
            *(unsigned*)(Ps + (size_t)(w * 16 + lr + 8) * FPH + nb * 8 + 2*lc) = pk2(p2, p3);
        }
        sum0 += __shfl_xor_sync(~0u, sum0, 1);
        sum0 += __shfl_xor_sync(~0u, sum0, 2);
        sum1 += __shfl_xor_sync(~0u, sum1, 1);
        sum1 += __shfl_xor_sync(~0u, sum1, 2);
        l0 = l0 * al0 + sum0; l1 = l1 * al1 + sum1;
        m0 = mn0; m1 = mn1;
        #pragma unroll
        for (int nb = 0; nb < 8; nb++) {
            oacc[nb][0] *= al0; oacc[nb][1] *= al0;
            oacc[nb][2] *= al1; oacc[nb][3] *= al1;
        }
        __syncwarp();

        #pragma unroll
        for (int kk = 0; kk < 4; kk++) {
            int kb = kk * 16;
            unsigned af[4];
            af[0] = *(const unsigned*)(Ps + (size_t)(w * 16 + lr) * FPH + kb + 2*lc);
            af[1] = *(const unsigned*)(Ps + (size_t)(w * 16 + lr + 8) * FPH + kb + 2*lc);
            af[2] = *(const unsigned*)(Ps + (size_t)(w * 16 + lr) * FPH + kb + 2*lc + 8);
            af[3] = *(const unsigned*)(Ps + (size_t)(w * 16 + lr + 8) * FPH + kb + 2*lc + 8);
            #pragma unroll
            for (int nb = 0; nb < 8; nb++) {
                unsigned bf[2];
                bf[0] = *(const unsigned*)(Vs + (size_t)(nb * 8 + lr) * FPH + kb + 2*lc);
                bf[1] = *(const unsigned*)(Vs + (size_t)(nb * 8 + lr) * FPH + kb + 2*lc + 8);
                mma_f16(oacc[nb], af, bf);
            }
        }
    }
    #undef LOAD_KV

    int batch = bh >> 4, h = bh & 15;
    float inv0 = 1.0f / l0, inv1 = 1.0f / l1;
    int t0 = qb * 64 + w * 16 + lr;
    #pragma unroll
    for (int nb = 0; nb < 8; nb++) {
        int d0 = h * HD + nb * 8 + 2 * lc;
        *(unsigned*)(Aout + ((size_t)batch * TT + t0) * HH + d0)     = pk2(oacc[nb][0] * inv0, oacc[nb][1] * inv0);
        *(unsigned*)(Aout + ((size_t)batch * TT + t0 + 8) * HH + d0) = pk2(oacc[nb][2] * inv1, oacc[nb][3] * inv1);
    }
}

// ---------------------------------------------------------------------------
// Launch
// ---------------------------------------------------------------------------
extern "C" void kernel_launch(void* const* d_in, const int* in_sizes, int n_in,
                              void* d_out, int out_size)
{
    const float* x       = (const float*)d_in[0];
    const float* w_attn  = (const float*)d_in[1];
    const float* b_attn  = (const float*)d_in[2];
    const float* w_aproj = (const float*)d_in[3];
    const float* b_aproj = (const float*)d_in[4];
    const float* ln1_w   = (const float*)d_in[5];
    const float* ln1_b   = (const float*)d_in[6];
    const float* ln2_w   = (const float*)d_in[7];
    const float* ln2_b   = (const float*)d_in[8];
    const float* w_fc    = (const float*)d_in[9];
    const float* b_fc    = (const float*)d_in[10];
    const float* w_mproj = (const float*)d_in[11];
    const float* b_mproj = (const float*)d_in[12];

    float* out_x = (float*)d_out;
    float* pk = out_x + (size_t)MM * HH;
    float* pv = pk + (size_t)MM * HH;

    __half *xn, *q, *kr, *vt, *a, *h, *wattnT, *waprojT, *wfcT, *wmprojT;
    float *x1, *part;
    cudaGetSymbolAddress((void**)&xn, g_xn);
    cudaGetSymbolAddress((void**)&q,  g_q);
    cudaGetSymbolAddress((void**)&kr, g_kr);
    cudaGetSymbolAddress((void**)&vt, g_vt);
    cudaGetSymbolAddress((void**)&a,  g_a);
    cudaGetSymbolAddress((void**)&x1, g_x1);
    cudaGetSymbolAddress((void**)&h,  g_h);
    cudaGetSymbolAddress((void**)&part, g_part);
    cudaGetSymbolAddress((void**)&wattnT,  g_wattnT);
    cudaGetSymbolAddress((void**)&waprojT, g_waprojT);
    cudaGetSymbolAddress((void**)&wfcT,    g_wfcT);
    cudaGetSymbolAddress((void**)&wmprojT, g_wmprojT);

    size_t gsmem = NSTAGE * STG_BYTES;   // 110592 B
    cudaFuncSetAttribute(tgemm_kernel<0>, cudaFuncAttributeMaxDynamicSharedMemorySize, (int)gsmem);
    cudaFuncSetAttribute(tgemm_kernel<1>, cudaFuncAttributeMaxDynamicSharedMemorySize, (int)gsmem);
    cudaFuncSetAttribute(tgemm_kernel<2>, cudaFuncAttributeMaxDynamicSharedMemorySize, (int)gsmem);
    size_t fsmem = 5 * FTILEH * 2;       // 46080 B
    cudaFuncSetAttribute(flash_kernel, cudaFuncAttributeMaxDynamicSharedMemorySize, (int)fsmem);

    pack_all_kernel<<<3072, 256>>>(w_attn, w_aproj, w_fc, w_mproj,
                                   wattnT, waprojT, wfcT, wmprojT);

    gn_stats_kernel<<<512, 256>>>(x, part);
    gn_apply_kernel<<<1024, 256>>>(x, part, ln1_w, ln1_b, xn);

    tgemm_kernel<0><<<dim3(3 * HH / GBN, MM / GBM), 256, gsmem>>>(
        xn, wattnT, b_attn, nullptr, nullptr, pk, pv, q, kr, vt, MM, 3 * HH, HH);

    flash_kernel<<<dim3(TT / 64, BB * NH), 128, fsmem>>>(q, kr, vt, a);

    tgemm_kernel<1><<<dim3(HH / GBN, MM / GBM), 256, gsmem>>>(
        a, waprojT, b_aproj, x, x1, nullptr, nullptr, nullptr, nullptr, nullptr, MM, HH, HH);

    gn_stats_kernel<<<512, 256>>>(x1, part);
    gn_apply_kernel<<<1024, 256>>>(x1, part, ln2_w, ln2_b, xn);

    tgemm_kernel<2><<<dim3(4 * HH / GBN, MM / GBM), 256, gsmem>>>(
        xn, wfcT, b_fc, nullptr, nullptr, nullptr, nullptr, h, nullptr, nullptr, MM, 4 * HH, HH);

    tgemm_kernel<1><<<dim3(HH / GBN, MM / GBM), 256, gsmem>>>(
        h, wmprojT, b_mproj, x1, out_x, nullptr, nullptr, nullptr, nullptr, nullptr, MM, HH, 4 * HH);
}